// round 2
// baseline (speedup 1.0000x reference)
#include <cuda_runtime.h>

// Problem constants (shapes fixed by reference setup_inputs)
#define BB 2
#define TT 32
#define HW 268324            // 518*518
#define QV (HW/4)            // 67081 float4 per frame
#define NQ (TT*HW)           // per-batch elements 8,586,368
#define NQ4 (TT*QV)          // per-batch float4 count
#define NROWS (BB*(TT-1))    // 62 frame-pair rows
#define NCHUNK 4             // time-chunks per (b,q) in pair kernel
#define EPSF 1e-6f
#define STATIC_TH 0.05f

// ---------------- device scratch (static, no allocations) ----------------
__device__ double       g_sums[BB][5];        // count, Sr, Sg, Srg, Srr
__device__ float        g_scale[BB], g_shift[BB];
__device__ unsigned int g_cnt[NROWS];
__device__ float        g_vals[NROWS][HW];    // compacted static err values (~63.5 MB)
__device__ float        g_loss[NROWS];

// ---------------- helpers ----------------
__inline__ __device__ float warp_sum(float v) {
    #pragma unroll
    for (int o = 16; o; o >>= 1) v += __shfl_down_sync(0xFFFFFFFFu, v, o);
    return v;
}

// ---------------- kernel 0: init ----------------
__global__ void k_init() {
    int t = threadIdx.x;
    if (t < BB * 5) ((double*)g_sums)[t] = 0.0;
    if (t < NROWS) g_cnt[t] = 0u;
}

// ---------------- kernel 1: per-batch masked sums ----------------
__global__ void k_reduce(const float* __restrict__ pred,
                         const float* __restrict__ depth,
                         const int* __restrict__ mask) {
    const int b = blockIdx.y;
    const float4* p4 = (const float4*)pred  + (size_t)b * NQ4;
    const float4* d4 = (const float4*)depth + (size_t)b * NQ4;
    const int4*   m4 = (const int4*)mask    + (size_t)b * NQ4;

    float c = 0.f, sr = 0.f, sg = 0.f, srg = 0.f, srr = 0.f;
    for (int i = blockIdx.x * blockDim.x + threadIdx.x; i < NQ4;
         i += gridDim.x * blockDim.x) {
        float4 pv = p4[i];
        float4 dv = d4[i];
        int4   mv = m4[i];
        float pa[4] = {pv.x, pv.y, pv.z, pv.w};
        float da[4] = {dv.x, dv.y, dv.z, dv.w};
        int   ma[4] = {mv.x, mv.y, mv.z, mv.w};
        #pragma unroll
        for (int l = 0; l < 4; l++) {
            if (ma[l]) {
                float r = fmaxf(pa[l], EPSF);
                float g = 1.0f / fmaxf(da[l], EPSF);
                c += 1.0f; sr += r; sg += g; srg += r * g; srr += r * r;
            }
        }
    }
    // block reduce 5 floats -> double atomics
    __shared__ float sh[5][8];
    int lane = threadIdx.x & 31, wid = threadIdx.x >> 5;
    c = warp_sum(c); sr = warp_sum(sr); sg = warp_sum(sg);
    srg = warp_sum(srg); srr = warp_sum(srr);
    if (lane == 0) { sh[0][wid]=c; sh[1][wid]=sr; sh[2][wid]=sg; sh[3][wid]=srg; sh[4][wid]=srr; }
    __syncthreads();
    if (wid == 0) {
        int nw = blockDim.x >> 5;
        float v0 = (lane < nw) ? sh[0][lane] : 0.f;
        float v1 = (lane < nw) ? sh[1][lane] : 0.f;
        float v2 = (lane < nw) ? sh[2][lane] : 0.f;
        float v3 = (lane < nw) ? sh[3][lane] : 0.f;
        float v4 = (lane < nw) ? sh[4][lane] : 0.f;
        v0 = warp_sum(v0); v1 = warp_sum(v1); v2 = warp_sum(v2);
        v3 = warp_sum(v3); v4 = warp_sum(v4);
        if (lane == 0) {
            atomicAdd(&g_sums[b][0], (double)v0);
            atomicAdd(&g_sums[b][1], (double)v1);
            atomicAdd(&g_sums[b][2], (double)v2);
            atomicAdd(&g_sums[b][3], (double)v3);
            atomicAdd(&g_sums[b][4], (double)v4);
        }
    }
}

// ---------------- kernel 2: solve scale/shift ----------------
__global__ void k_solve() {
    int b = threadIdx.x;
    if (b < BB) {
        double cnt = g_sums[b][0]; if (cnt < 1.0) cnt = 1.0;
        double mr = g_sums[b][1] / cnt;
        double mg = g_sums[b][2] / cnt;
        double cov = g_sums[b][3] - cnt * mr * mg;
        double var = g_sums[b][4] - cnt * mr * mr;
        if (var < (double)EPSF) var = (double)EPSF;
        double s = cov / var;
        g_scale[b] = (float)s;
        g_shift[b] = (float)(mg - s * mr);
    }
}

// ---------------- kernel 3: pair errors + compaction ----------------
__global__ void k_pairs(const float* __restrict__ pred,
                        const float* __restrict__ depth,
                        const int* __restrict__ mask) {
    int idx = blockIdx.x * blockDim.x + threadIdx.x;
    if (idx >= BB * NCHUNK * QV) return;
    int q = idx % QV;
    int c = (idx / QV) % NCHUNK;
    int b = idx / (NCHUNK * QV);

    int t0 = c * 8;                       // chunk covers pairs [t0, t0+np)
    int np = min(8, (TT - 1) - t0);       // 8,8,8,7

    const float4* p4 = (const float4*)pred;
    const float4* d4 = (const float4*)depth;
    const int4*   m4 = (const int4*)mask;
    size_t off = (size_t)b * NQ4 + (size_t)t0 * QV + q;

    const float sc = g_scale[b];
    const float tc = g_shift[b];

    float4 pv = p4[off]; float4 dv = d4[off]; int4 mv = m4[off];
    float rp[4], gp[4], dp[4]; int mp[4];
    {
        float pa[4] = {pv.x, pv.y, pv.z, pv.w};
        float da[4] = {dv.x, dv.y, dv.z, dv.w};
        int   ma[4] = {mv.x, mv.y, mv.z, mv.w};
        #pragma unroll
        for (int l = 0; l < 4; l++) {
            rp[l] = fmaxf(pa[l], EPSF);
            gp[l] = 1.0f / fmaxf(da[l], EPSF);
            dp[l] = da[l]; mp[l] = ma[l];
        }
    }

    for (int i = 1; i <= np; i++) {
        off += QV;
        pv = p4[off]; dv = d4[off]; mv = m4[off];
        float pa[4] = {pv.x, pv.y, pv.z, pv.w};
        float da[4] = {dv.x, dv.y, dv.z, dv.w};
        int   ma[4] = {mv.x, mv.y, mv.z, mv.w};
        int row = b * (TT - 1) + t0 + i - 1;
        #pragma unroll
        for (int l = 0; l < 4; l++) {
            float r = fmaxf(pa[l], EPSF);
            float g = 1.0f / fmaxf(da[l], EPSF);
            if (mp[l] && ma[l] && fabsf(da[l] - dp[l]) < STATIC_TH) {
                float a0 = rp[l] * sc + tc;
                float a1 = r * sc + tc;
                float err = fabsf(fabsf(a1 - a0) - fabsf(g - gp[l]));
                unsigned pos = atomicAdd(&g_cnt[row], 1u);
                g_vals[row][pos] = err;
            }
            rp[l] = r; gp[l] = g; dp[l] = da[l]; mp[l] = ma[l];
        }
    }
}

// ---------------- per-row exact radix select (nonneg float bits) ----------------
__device__ float radix_kth(const float* v, int nv, int k,
                           unsigned int* hist, unsigned int* sh_prefix, int* sh_rank) {
    if (threadIdx.x == 0) { *sh_prefix = 0u; *sh_rank = k; }
    __syncthreads();
    #pragma unroll
    for (int pass = 0; pass < 4; pass++) {
        int shift = 24 - 8 * pass;
        for (int i = threadIdx.x; i < 256; i += blockDim.x) hist[i] = 0u;
        __syncthreads();
        unsigned pfx = *sh_prefix;
        unsigned hmask = (pass == 0) ? 0u : (0xFFFFFFFFu << (shift + 8));
        for (int i = threadIdx.x; i < nv; i += blockDim.x) {
            unsigned key = __float_as_uint(v[i]);
            if ((key & hmask) == pfx)
                atomicAdd(&hist[(key >> shift) & 255u], 1u);
        }
        __syncthreads();
        if (threadIdx.x == 0) {
            unsigned cum = 0; int r = *sh_rank;
            for (int d = 0; d < 256; d++) {
                unsigned h = hist[d];
                if (cum + h > (unsigned)r) {
                    *sh_prefix = pfx | ((unsigned)d << shift);
                    *sh_rank = r - (int)cum;
                    break;
                }
                cum += h;
            }
        }
        __syncthreads();
    }
    return __uint_as_float(*sh_prefix);
}

// ---------------- kernel 4: per-row quantile + trimmed mean ----------------
__global__ void k_select() {
    int row = blockIdx.x;
    int nv = (int)g_cnt[row];
    const float* v = g_vals[row];
    __shared__ unsigned int hist[256];
    __shared__ unsigned int sh_prefix;
    __shared__ int sh_rank;
    __shared__ float sh_f[8];
    __shared__ int sh_i[8];

    if (nv == 0) {
        if (threadIdx.x == 0) g_loss[row] = 0.0f;   // cnt clamped to 1, sum 0
        return;
    }
    float pos = 0.8f * (float)(nv - 1);
    float fl = floorf(pos);
    int lo = (int)fl;
    int hi = (int)ceilf(pos);
    float frac = pos - fl;

    float vlo = radix_kth(v, nv, lo, hist, &sh_prefix, &sh_rank);
    float vhi = (hi == lo) ? vlo : radix_kth(v, nv, hi, hist, &sh_prefix, &sh_rank);
    float thresh = vlo * (1.0f - frac) + vhi * frac;

    float ssum = 0.f; int scnt = 0;
    for (int i = threadIdx.x; i < nv; i += blockDim.x) {
        float x = v[i];
        if (x <= thresh) { ssum += x; scnt++; }
    }
    int lane = threadIdx.x & 31, wid = threadIdx.x >> 5;
    ssum = warp_sum(ssum);
    #pragma unroll
    for (int o = 16; o; o >>= 1) scnt += __shfl_down_sync(0xFFFFFFFFu, scnt, o);
    if (lane == 0) { sh_f[wid] = ssum; sh_i[wid] = scnt; }
    __syncthreads();
    if (threadIdx.x == 0) {
        float s = 0.f; int c = 0;
        int nw = blockDim.x >> 5;
        for (int w = 0; w < nw; w++) { s += sh_f[w]; c += sh_i[w]; }
        g_loss[row] = s / fmaxf((float)c, 1.0f);
    }
}

// ---------------- kernel 5: mean over rows ----------------
__global__ void k_final(float* __restrict__ out) {
    __shared__ float sh[64];
    float a = 0.f;
    for (int i = threadIdx.x; i < NROWS; i += 64) a += g_loss[i];
    sh[threadIdx.x] = a;
    __syncthreads();
    if (threadIdx.x == 0) {
        float t = 0.f;
        for (int i = 0; i < 64; i++) t += sh[i];
        out[0] = t / (float)NROWS;
    }
}

// ---------------- launch ----------------
extern "C" void kernel_launch(void* const* d_in, const int* in_sizes, int n_in,
                              void* d_out, int out_size) {
    const float* pred  = (const float*)d_in[0];
    const float* depth = (const float*)d_in[1];
    const int*   mask  = (const int*)d_in[2];
    float* out = (float*)d_out;

    k_init<<<1, 128>>>();

    dim3 rgrid(1024, BB);
    k_reduce<<<rgrid, 256>>>(pred, depth, mask);

    k_solve<<<1, 32>>>();

    int npairs_threads = BB * NCHUNK * QV;
    k_pairs<<<(npairs_threads + 255) / 256, 256>>>(pred, depth, mask);

    k_select<<<NROWS, 256>>>();

    k_final<<<1, 64>>>(out);
}